// round 1
// baseline (speedup 1.0000x reference)
#include <cuda_runtime.h>
#include <cuda_bf16.h>
#include <math.h>

// Problem constants
#define SEQ   4096
#define DIM   1024
#define C3    3072          // 3*DIM
#define NHEAD 16
#define HD    64
#define SCALE 0.125f        // 64^-0.5

// Scratch (device globals; allocation-free per harness rules)
__device__ float g_qkv[SEQ * C3];     // 48 MB
__device__ float g_att[SEQ * DIM];    // 16 MB

// ---------------------------------------------------------------------------
// SGEMM: C[M,N] = A[M,K] @ B[N,K]^T (+ bias). A,B row-major. All dims %128==0,
// K%16==0. 256 threads, BM=BN=128, BK=16, 8x8 micro-tile per thread.
// ---------------------------------------------------------------------------
#define BM 128
#define BN 128
#define BK 16
#define TM 8
#define TN 8

__global__ __launch_bounds__(256, 2)
void sgemm_nt(const float* __restrict__ A, const float* __restrict__ B,
              const float* __restrict__ bias, float* __restrict__ C,
              int M, int N, int K)
{
    __shared__ float As[BK][BM];
    __shared__ float Bs[BK][BN];

    const int bx = blockIdx.x;   // N tile
    const int by = blockIdx.y;   // M tile
    const int tid = threadIdx.x;
    const int tx = tid & 15;     // 16 along N
    const int ty = tid >> 4;     // 16 along M

    float acc[TM][TN];
#pragma unroll
    for (int i = 0; i < TM; i++)
#pragma unroll
        for (int j = 0; j < TN; j++) acc[i][j] = 0.f;

    // loading map: 64 rows per pass, 4 float4 (=16 floats = BK) per row
    const int lRow  = tid >> 2;     // 0..63
    const int lCol4 = tid & 3;      // 0..3

    const float* Abase = A + (size_t)(by * BM) * K;
    const float* Bbase = B + (size_t)(bx * BN) * K;

    for (int k0 = 0; k0 < K; k0 += BK) {
#pragma unroll
        for (int half = 0; half < 2; half++) {
            const int r = lRow + half * 64;
            float4 av = *(const float4*)&Abase[(size_t)r * K + k0 + lCol4 * 4];
            As[lCol4 * 4 + 0][r] = av.x;
            As[lCol4 * 4 + 1][r] = av.y;
            As[lCol4 * 4 + 2][r] = av.z;
            As[lCol4 * 4 + 3][r] = av.w;
            float4 bv = *(const float4*)&Bbase[(size_t)r * K + k0 + lCol4 * 4];
            Bs[lCol4 * 4 + 0][r] = bv.x;
            Bs[lCol4 * 4 + 1][r] = bv.y;
            Bs[lCol4 * 4 + 2][r] = bv.z;
            Bs[lCol4 * 4 + 3][r] = bv.w;
        }
        __syncthreads();

#pragma unroll
        for (int kk = 0; kk < BK; kk++) {
            float ra[TM], rb[TN];
#pragma unroll
            for (int i = 0; i < TM; i++) ra[i] = As[kk][ty * TM + i];
#pragma unroll
            for (int j = 0; j < TN; j++) rb[j] = Bs[kk][tx * TN + j];
#pragma unroll
            for (int i = 0; i < TM; i++)
#pragma unroll
                for (int j = 0; j < TN; j++)
                    acc[i][j] = fmaf(ra[i], rb[j], acc[i][j]);
        }
        __syncthreads();
    }

#pragma unroll
    for (int i = 0; i < TM; i++) {
        const int row = by * BM + ty * TM + i;
        float* crow = C + (size_t)row * N + bx * BN + tx * TN;
#pragma unroll
        for (int j4 = 0; j4 < TN / 4; j4++) {
            float4 v;
            v.x = acc[i][j4 * 4 + 0];
            v.y = acc[i][j4 * 4 + 1];
            v.z = acc[i][j4 * 4 + 2];
            v.w = acc[i][j4 * 4 + 3];
            if (bias) {
                const float* bsrc = bias + bx * BN + tx * TN + j4 * 4;
                v.x += bsrc[0]; v.y += bsrc[1]; v.z += bsrc[2]; v.w += bsrc[3];
            }
            *(float4*)&crow[j4 * 4] = v;
        }
    }
}

// ---------------------------------------------------------------------------
// Flash attention (fp32). Grid: (SEQ/64, NHEAD). 256 threads.
// Each CTA: 64 query rows of one head; loops 64-key tiles with online softmax.
// Thread map 16x16: S/P/O 4x4 micro-tile (rows ty*4+i, cols tx*4+j).
// Dynamic smem: Qs,Ks,Vs,Ps each [64][65] floats = 66560 B total.
// ---------------------------------------------------------------------------
#define AQ 64
#define AK 64
#define LDP 65

__global__ __launch_bounds__(256, 2)
void attn_kernel(const float* __restrict__ qkv, float* __restrict__ out)
{
    extern __shared__ float smem[];
    float* Qs = smem;                  // [AQ][LDP]
    float* Ks = Qs + AQ * LDP;         // [AK][LDP]
    float* Vs = Ks + AK * LDP;         // [AK][LDP]
    float* Ps = Vs + AK * LDP;         // [AQ][LDP]

    const int h   = blockIdx.y;
    const int qb  = blockIdx.x;
    const int tid = threadIdx.x;
    const int tx  = tid & 15;
    const int ty  = tid >> 4;

    const int qcol = h * HD;              // q columns in qkv
    const int kcol = DIM + h * HD;        // k columns
    const int vcol = 2 * DIM + h * HD;    // v columns

    // Load Q (pre-scaled). 64x64 floats = 1024 float4, 4 per thread.
    for (int idx = tid; idx < AQ * HD / 4; idx += 256) {
        const int r  = idx >> 4;          // 16 float4 per row
        const int c4 = idx & 15;
        float4 v = *(const float4*)&qkv[(size_t)(qb * AQ + r) * C3 + qcol + c4 * 4];
        Qs[r * LDP + c4 * 4 + 0] = v.x * SCALE;
        Qs[r * LDP + c4 * 4 + 1] = v.y * SCALE;
        Qs[r * LDP + c4 * 4 + 2] = v.z * SCALE;
        Qs[r * LDP + c4 * 4 + 3] = v.w * SCALE;
    }

    float m_i[4], l_i[4], O[4][4];
#pragma unroll
    for (int i = 0; i < 4; i++) {
        m_i[i] = -1e30f;
        l_i[i] = 0.f;
#pragma unroll
        for (int j = 0; j < 4; j++) O[i][j] = 0.f;
    }
    __syncthreads();

    for (int kt = 0; kt < SEQ / AK; kt++) {
        // Load K and V tiles
        for (int idx = tid; idx < AK * HD / 4; idx += 256) {
            const int r  = idx >> 4;
            const int c4 = idx & 15;
            const size_t rowoff = (size_t)(kt * AK + r) * C3;
            float4 kv = *(const float4*)&qkv[rowoff + kcol + c4 * 4];
            Ks[r * LDP + c4 * 4 + 0] = kv.x;
            Ks[r * LDP + c4 * 4 + 1] = kv.y;
            Ks[r * LDP + c4 * 4 + 2] = kv.z;
            Ks[r * LDP + c4 * 4 + 3] = kv.w;
            float4 vv = *(const float4*)&qkv[rowoff + vcol + c4 * 4];
            Vs[r * LDP + c4 * 4 + 0] = vv.x;
            Vs[r * LDP + c4 * 4 + 1] = vv.y;
            Vs[r * LDP + c4 * 4 + 2] = vv.z;
            Vs[r * LDP + c4 * 4 + 3] = vv.w;
        }
        __syncthreads();

        // S = Qs @ Ks^T (4x4 per thread)
        float s[4][4];
#pragma unroll
        for (int i = 0; i < 4; i++)
#pragma unroll
            for (int j = 0; j < 4; j++) s[i][j] = 0.f;
#pragma unroll 8
        for (int k = 0; k < HD; k++) {
            float qa[4], kb[4];
#pragma unroll
            for (int i = 0; i < 4; i++) qa[i] = Qs[(ty * 4 + i) * LDP + k];
#pragma unroll
            for (int j = 0; j < 4; j++) kb[j] = Ks[(tx * 4 + j) * LDP + k];
#pragma unroll
            for (int i = 0; i < 4; i++)
#pragma unroll
                for (int j = 0; j < 4; j++)
                    s[i][j] = fmaf(qa[i], kb[j], s[i][j]);
        }

        // Online softmax per row group
#pragma unroll
        for (int i = 0; i < 4; i++) {
            float mx = fmaxf(fmaxf(s[i][0], s[i][1]), fmaxf(s[i][2], s[i][3]));
#pragma unroll
            for (int off = 8; off > 0; off >>= 1)
                mx = fmaxf(mx, __shfl_xor_sync(0xffffffffu, mx, off, 16));
            const float newm = fmaxf(m_i[i], mx);
            const float alpha = __expf(m_i[i] - newm);
            m_i[i] = newm;
            float rs = 0.f;
#pragma unroll
            for (int j = 0; j < 4; j++) {
                const float p = __expf(s[i][j] - newm);
                Ps[(ty * 4 + i) * LDP + tx * 4 + j] = p;
                rs += p;
            }
#pragma unroll
            for (int off = 8; off > 0; off >>= 1)
                rs += __shfl_xor_sync(0xffffffffu, rs, off, 16);
            l_i[i] = l_i[i] * alpha + rs;
#pragma unroll
            for (int j = 0; j < 4; j++) O[i][j] *= alpha;
        }
        __syncthreads();

        // O += Ps @ Vs
#pragma unroll 8
        for (int c = 0; c < AK; c++) {
            float pa[4], vb[4];
#pragma unroll
            for (int i = 0; i < 4; i++) pa[i] = Ps[(ty * 4 + i) * LDP + c];
#pragma unroll
            for (int j = 0; j < 4; j++) vb[j] = Vs[c * LDP + tx * 4 + j];
#pragma unroll
            for (int i = 0; i < 4; i++)
#pragma unroll
                for (int j = 0; j < 4; j++)
                    O[i][j] = fmaf(pa[i], vb[j], O[i][j]);
        }
        __syncthreads();
    }

    // Epilogue: normalize and write [SEQ, DIM] layout (row n, col h*64+d)
#pragma unroll
    for (int i = 0; i < 4; i++) {
        const float inv = 1.f / l_i[i];
        const int row = qb * AQ + ty * 4 + i;
        float* dst = out + (size_t)row * DIM + h * HD + tx * 4;
        float4 v;
        v.x = O[i][0] * inv; v.y = O[i][1] * inv;
        v.z = O[i][2] * inv; v.w = O[i][3] * inv;
        *(float4*)dst = v;
    }
}

// ---------------------------------------------------------------------------
extern "C" void kernel_launch(void* const* d_in, const int* in_sizes, int n_in,
                              void* d_out, int out_size)
{
    const float* x      = (const float*)d_in[0];   // [4096, 3072]
    const float* W_qkv  = (const float*)d_in[1];   // [3072, 3072]
    const float* W_proj = (const float*)d_in[2];   // [1024, 1024]
    const float* b_proj = (const float*)d_in[3];   // [1024]
    float* out = (float*)d_out;                    // [4096, 1024]

    float* qkv; cudaGetSymbolAddress((void**)&qkv, g_qkv);
    float* att; cudaGetSymbolAddress((void**)&att, g_att);

    static bool attr_done = false;
    if (!attr_done) {
        cudaFuncSetAttribute(attn_kernel,
                             cudaFuncAttributeMaxDynamicSharedMemorySize,
                             4 * AQ * LDP * (int)sizeof(float));
        attr_done = true;
    }

    // 1) qkv = x @ W_qkv^T
    {
        dim3 grid(C3 / BN, SEQ / BM);
        sgemm_nt<<<grid, 256>>>(x, W_qkv, nullptr, qkv, SEQ, C3, C3);
    }
    // 2) attention
    {
        dim3 grid(SEQ / AQ, NHEAD);
        attn_kernel<<<grid, 256, 4 * AQ * LDP * (int)sizeof(float)>>>(qkv, att);
    }
    // 3) out = att @ W_proj^T + b_proj
    {
        dim3 grid(DIM / BN, SEQ / BM);
        sgemm_nt<<<grid, 256>>>(att, W_proj, b_proj, out, SEQ, DIM, DIM);
    }
}

// round 2
// speedup vs baseline: 3.3698x; 3.3698x over previous
#include <cuda_runtime.h>
#include <cuda_bf16.h>
#include <math.h>
#include <stdint.h>

// Problem constants
#define SEQ   4096
#define DIM   1024
#define C3    3072          // 3*DIM
#define NHEAD 16
#define HD    64
#define SCALE 0.125f        // 64^-0.5

// Scratch (device globals; allocation-free per harness rules)
__device__ float g_qkv[SEQ * C3];     // 48 MB
__device__ float g_att[SEQ * DIM];    // 16 MB

// ---------------------------------------------------------------------------
// Helpers
// ---------------------------------------------------------------------------
__device__ __forceinline__ float to_tf32(float x) {
    float r;
    asm("cvt.rna.tf32.f32 %0, %1;" : "=f"(r) : "f"(x));
    return r;
}

__device__ __forceinline__ void mma_tf32(float* c,
                                         uint32_t a0, uint32_t a1, uint32_t a2, uint32_t a3,
                                         uint32_t b0, uint32_t b1) {
    asm volatile(
        "mma.sync.aligned.m16n8k8.row.col.f32.tf32.tf32.f32 "
        "{%0,%1,%2,%3}, {%4,%5,%6,%7}, {%8,%9}, {%0,%1,%2,%3};"
        : "+f"(c[0]), "+f"(c[1]), "+f"(c[2]), "+f"(c[3])
        : "r"(a0), "r"(a1), "r"(a2), "r"(a3), "r"(b0), "r"(b1));
}

__device__ __forceinline__ uint32_t f2u(float x) { return __float_as_uint(x); }

// ---------------------------------------------------------------------------
// TF32 tensor-core GEMM: C[M,N] = A[M,K] @ B[N,K]^T (+bias)
// 256 threads = 8 warps (4 m x 2 n). CTA tile 128x128, BK=16.
// Warp tile 32x64 -> mma grid 2(m) x 8(n), 2 k-steps of 8.
// smem stride 20 floats -> fragment loads conflict-free ((20g+tig)%32 distinct)
// ---------------------------------------------------------------------------
#define BM 128
#define BN 128
#define BK 16
#define BKP 20

__global__ __launch_bounds__(256, 2)
void gemm_tf32(const float* __restrict__ A, const float* __restrict__ B,
               const float* __restrict__ bias, float* __restrict__ C,
               int M, int N, int K)
{
    __shared__ float As[BM][BKP];
    __shared__ float Bs[BN][BKP];

    const int bx = blockIdx.x;        // N tile
    const int by = blockIdx.y;        // M tile
    const int tid = threadIdx.x;
    const int lane = tid & 31;
    const int wid = tid >> 5;
    const int wm = wid >> 1;          // 0..3
    const int wn = wid & 1;           // 0..1
    const int g = lane >> 2;          // 0..7
    const int tig = lane & 3;         // 0..3

    const int lr = tid >> 2;          // 0..63 (load row)
    const int lc4 = tid & 3;          // 0..3  (load float4 col)

    const float* Abase = A + (size_t)(by * BM) * K;
    const float* Bbase = B + (size_t)(bx * BN) * K;

    float acc[2][8][4];
#pragma unroll
    for (int mi = 0; mi < 2; mi++)
#pragma unroll
        for (int ni = 0; ni < 8; ni++)
#pragma unroll
            for (int r = 0; r < 4; r++) acc[mi][ni][r] = 0.f;

    // Prologue: load tile 0 into smem (tf32-converted)
#pragma unroll
    for (int h = 0; h < 2; h++) {
        const int r = lr + h * 64;
        float4 av = *(const float4*)&Abase[(size_t)r * K + lc4 * 4];
        As[r][lc4 * 4 + 0] = to_tf32(av.x);
        As[r][lc4 * 4 + 1] = to_tf32(av.y);
        As[r][lc4 * 4 + 2] = to_tf32(av.z);
        As[r][lc4 * 4 + 3] = to_tf32(av.w);
        float4 bv = *(const float4*)&Bbase[(size_t)r * K + lc4 * 4];
        Bs[r][lc4 * 4 + 0] = to_tf32(bv.x);
        Bs[r][lc4 * 4 + 1] = to_tf32(bv.y);
        Bs[r][lc4 * 4 + 2] = to_tf32(bv.z);
        Bs[r][lc4 * 4 + 3] = to_tf32(bv.w);
    }
    __syncthreads();

    const int nTiles = K / BK;
    for (int kt = 0; kt < nTiles; kt++) {
        // Prefetch next tile into registers
        float4 aN[2], bN[2];
        if (kt + 1 < nTiles) {
            const int k0 = (kt + 1) * BK;
#pragma unroll
            for (int h = 0; h < 2; h++) {
                const int r = lr + h * 64;
                aN[h] = *(const float4*)&Abase[(size_t)r * K + k0 + lc4 * 4];
                bN[h] = *(const float4*)&Bbase[(size_t)r * K + k0 + lc4 * 4];
            }
        }

        // Compute on current tile
#pragma unroll
        for (int ks = 0; ks < 2; ks++) {
            const int kb = ks * 8;
            uint32_t af[2][4];
#pragma unroll
            for (int mi = 0; mi < 2; mi++) {
                const int rb = wm * 32 + mi * 16;
                af[mi][0] = f2u(As[rb + g][kb + tig]);
                af[mi][1] = f2u(As[rb + g + 8][kb + tig]);
                af[mi][2] = f2u(As[rb + g][kb + tig + 4]);
                af[mi][3] = f2u(As[rb + g + 8][kb + tig + 4]);
            }
            uint32_t bf[8][2];
#pragma unroll
            for (int ni = 0; ni < 8; ni++) {
                const int nb = wn * 64 + ni * 8;
                bf[ni][0] = f2u(Bs[nb + g][kb + tig]);
                bf[ni][1] = f2u(Bs[nb + g][kb + tig + 4]);
            }
#pragma unroll
            for (int mi = 0; mi < 2; mi++)
#pragma unroll
                for (int ni = 0; ni < 8; ni++)
                    mma_tf32(acc[mi][ni], af[mi][0], af[mi][1], af[mi][2], af[mi][3],
                             bf[ni][0], bf[ni][1]);
        }
        __syncthreads();

        if (kt + 1 < nTiles) {
#pragma unroll
            for (int h = 0; h < 2; h++) {
                const int r = lr + h * 64;
                As[r][lc4 * 4 + 0] = to_tf32(aN[h].x);
                As[r][lc4 * 4 + 1] = to_tf32(aN[h].y);
                As[r][lc4 * 4 + 2] = to_tf32(aN[h].z);
                As[r][lc4 * 4 + 3] = to_tf32(aN[h].w);
                Bs[r][lc4 * 4 + 0] = to_tf32(bN[h].x);
                Bs[r][lc4 * 4 + 1] = to_tf32(bN[h].y);
                Bs[r][lc4 * 4 + 2] = to_tf32(bN[h].z);
                Bs[r][lc4 * 4 + 3] = to_tf32(bN[h].w);
            }
            __syncthreads();
        }
    }

    // Epilogue: float2 stores per fragment half
#pragma unroll
    for (int mi = 0; mi < 2; mi++) {
#pragma unroll
        for (int ni = 0; ni < 8; ni++) {
            const int row0 = by * BM + wm * 32 + mi * 16 + g;
            const int col = bx * BN + wn * 64 + ni * 8 + 2 * tig;
            float b0 = 0.f, b1 = 0.f;
            if (bias) { b0 = bias[col]; b1 = bias[col + 1]; }
            float2 v0 = make_float2(acc[mi][ni][0] + b0, acc[mi][ni][1] + b1);
            float2 v1 = make_float2(acc[mi][ni][2] + b0, acc[mi][ni][3] + b1);
            *(float2*)&C[(size_t)row0 * N + col] = v0;
            *(float2*)&C[(size_t)(row0 + 8) * N + col] = v1;
        }
    }
}

// ---------------------------------------------------------------------------
// Flash attention, TF32 mma. Grid: (SEQ/64, NHEAD), 128 threads (4 warps).
// Each warp owns 16 q-rows. Per 64-key tile: S = Q K^T (mma), fragment-layout
// online softmax (quad shfl reductions), P staged via smem (layout change),
// O += P V (mma). Smem strides: Q/K/P = 68 (conflict-free A/B frag loads),
// V = 72 (conflict-free B frag loads in [k][n] layout).
// ---------------------------------------------------------------------------
#define AQ 64
#define AK 64
#define QKS 68
#define VSS 72
#define ATTN_SMEM ((3 * 64 * QKS + 64 * VSS) * 4)

__global__ __launch_bounds__(128, 2)
void attn_tf32(const float* __restrict__ qkv, float* __restrict__ out)
{
    extern __shared__ float sm[];
    float* Qs = sm;                    // [64][68]
    float* Ks = Qs + 64 * QKS;         // [64][68]
    float* Ps = Ks + 64 * QKS;         // [64][68]
    float* Vs = Ps + 64 * QKS;         // [64][72]  (layout [k][n])

    const int h = blockIdx.y;
    const int qb = blockIdx.x;
    const int tid = threadIdx.x;
    const int lane = tid & 31;
    const int w = tid >> 5;            // warp 0..3 -> q rows w*16..+16
    const int g = lane >> 2;
    const int tig = lane & 3;

    const int qcol = h * HD;
    const int kcol = DIM + h * HD;
    const int vcol = 2 * DIM + h * HD;

    // Load Q (scaled + tf32)
    for (int idx = tid; idx < AQ * HD / 4; idx += 128) {
        const int r = idx >> 4;
        const int c4 = idx & 15;
        float4 v = *(const float4*)&qkv[(size_t)(qb * AQ + r) * C3 + qcol + c4 * 4];
        Qs[r * QKS + c4 * 4 + 0] = to_tf32(v.x * SCALE);
        Qs[r * QKS + c4 * 4 + 1] = to_tf32(v.y * SCALE);
        Qs[r * QKS + c4 * 4 + 2] = to_tf32(v.z * SCALE);
        Qs[r * QKS + c4 * 4 + 3] = to_tf32(v.w * SCALE);
    }
    __syncthreads();

    // Hoist Q fragments: 8 k-steps x 4 regs
    uint32_t qf[8][4];
#pragma unroll
    for (int ks = 0; ks < 8; ks++) {
        const int kb = ks * 8;
        const int rb = w * 16;
        qf[ks][0] = f2u(Qs[(rb + g) * QKS + kb + tig]);
        qf[ks][1] = f2u(Qs[(rb + g + 8) * QKS + kb + tig]);
        qf[ks][2] = f2u(Qs[(rb + g) * QKS + kb + tig + 4]);
        qf[ks][3] = f2u(Qs[(rb + g + 8) * QKS + kb + tig + 4]);
    }

    float m0 = -1e30f, m1 = -1e30f, l0 = 0.f, l1 = 0.f;
    float o[8][4];
#pragma unroll
    for (int ni = 0; ni < 8; ni++)
#pragma unroll
        for (int r = 0; r < 4; r++) o[ni][r] = 0.f;

    for (int kt = 0; kt < SEQ / AK; kt++) {
        __syncthreads();   // protect Ks/Vs from previous iteration's readers
        // Load K,V tiles
        for (int idx = tid; idx < AK * HD / 4; idx += 128) {
            const int r = idx >> 4;
            const int c4 = idx & 15;
            const size_t ro = (size_t)(kt * AK + r) * C3;
            float4 kv = *(const float4*)&qkv[ro + kcol + c4 * 4];
            Ks[r * QKS + c4 * 4 + 0] = to_tf32(kv.x);
            Ks[r * QKS + c4 * 4 + 1] = to_tf32(kv.y);
            Ks[r * QKS + c4 * 4 + 2] = to_tf32(kv.z);
            Ks[r * QKS + c4 * 4 + 3] = to_tf32(kv.w);
            float4 vv = *(const float4*)&qkv[ro + vcol + c4 * 4];
            Vs[r * VSS + c4 * 4 + 0] = to_tf32(vv.x);
            Vs[r * VSS + c4 * 4 + 1] = to_tf32(vv.y);
            Vs[r * VSS + c4 * 4 + 2] = to_tf32(vv.z);
            Vs[r * VSS + c4 * 4 + 3] = to_tf32(vv.w);
        }
        __syncthreads();

        // S = Q K^T : 16 x 64 per warp
        float s[8][4];
#pragma unroll
        for (int ni = 0; ni < 8; ni++)
#pragma unroll
            for (int r = 0; r < 4; r++) s[ni][r] = 0.f;

#pragma unroll
        for (int ks = 0; ks < 8; ks++) {
            const int kb = ks * 8;
            uint32_t bf[8][2];
#pragma unroll
            for (int ni = 0; ni < 8; ni++) {
                bf[ni][0] = f2u(Ks[(ni * 8 + g) * QKS + kb + tig]);
                bf[ni][1] = f2u(Ks[(ni * 8 + g) * QKS + kb + tig + 4]);
            }
#pragma unroll
            for (int ni = 0; ni < 8; ni++)
                mma_tf32(s[ni], qf[ks][0], qf[ks][1], qf[ks][2], qf[ks][3],
                         bf[ni][0], bf[ni][1]);
        }

        // Online softmax. Thread rows: r0 = g (c0,c1), r1 = g+8 (c2,c3)
        float mx0 = -1e30f, mx1 = -1e30f;
#pragma unroll
        for (int ni = 0; ni < 8; ni++) {
            mx0 = fmaxf(mx0, fmaxf(s[ni][0], s[ni][1]));
            mx1 = fmaxf(mx1, fmaxf(s[ni][2], s[ni][3]));
        }
#pragma unroll
        for (int off = 1; off < 4; off <<= 1) {
            mx0 = fmaxf(mx0, __shfl_xor_sync(0xffffffffu, mx0, off));
            mx1 = fmaxf(mx1, __shfl_xor_sync(0xffffffffu, mx1, off));
        }
        const float nm0 = fmaxf(m0, mx0);
        const float nm1 = fmaxf(m1, mx1);
        const float al0 = __expf(m0 - nm0);
        const float al1 = __expf(m1 - nm1);
        m0 = nm0; m1 = nm1;

        float rs0 = 0.f, rs1 = 0.f;
        const int pr0 = (w * 16 + g) * QKS;
        const int pr1 = (w * 16 + g + 8) * QKS;
#pragma unroll
        for (int ni = 0; ni < 8; ni++) {
            const float p0 = __expf(s[ni][0] - nm0);
            const float p1 = __expf(s[ni][1] - nm0);
            const float p2 = __expf(s[ni][2] - nm1);
            const float p3 = __expf(s[ni][3] - nm1);
            rs0 += p0 + p1;
            rs1 += p2 + p3;
            const int c = ni * 8 + 2 * tig;
            Ps[pr0 + c] = p0; Ps[pr0 + c + 1] = p1;
            Ps[pr1 + c] = p2; Ps[pr1 + c + 1] = p3;
        }
#pragma unroll
        for (int off = 1; off < 4; off <<= 1) {
            rs0 += __shfl_xor_sync(0xffffffffu, rs0, off);
            rs1 += __shfl_xor_sync(0xffffffffu, rs1, off);
        }
        l0 = l0 * al0 + rs0;
        l1 = l1 * al1 + rs1;
#pragma unroll
        for (int ni = 0; ni < 8; ni++) {
            o[ni][0] *= al0; o[ni][1] *= al0;
            o[ni][2] *= al1; o[ni][3] *= al1;
        }
        __syncwarp();   // Ps rows are warp-private: warp-level visibility only

        // O += P V : A-frags from Ps, B-frags from Vs[k][n]
#pragma unroll
        for (int ks = 0; ks < 8; ks++) {
            const int kb = ks * 8;
            uint32_t a0 = f2u(Ps[pr0 + kb + tig]);
            uint32_t a1 = f2u(Ps[pr1 + kb + tig]);
            uint32_t a2 = f2u(Ps[pr0 + kb + tig + 4]);
            uint32_t a3 = f2u(Ps[pr1 + kb + tig + 4]);
#pragma unroll
            for (int ni = 0; ni < 8; ni++) {
                uint32_t b0 = f2u(Vs[(kb + tig) * VSS + ni * 8 + g]);
                uint32_t b1 = f2u(Vs[(kb + tig + 4) * VSS + ni * 8 + g]);
                mma_tf32(o[ni], a0, a1, a2, a3, b0, b1);
            }
        }
    }

    // Epilogue
    const float inv0 = 1.f / l0;
    const float inv1 = 1.f / l1;
    const int row0 = qb * AQ + w * 16 + g;
#pragma unroll
    for (int ni = 0; ni < 8; ni++) {
        const int col = h * HD + ni * 8 + 2 * tig;
        *(float2*)&out[(size_t)row0 * DIM + col] =
            make_float2(o[ni][0] * inv0, o[ni][1] * inv0);
        *(float2*)&out[(size_t)(row0 + 8) * DIM + col] =
            make_float2(o[ni][2] * inv1, o[ni][3] * inv1);
    }
}

// ---------------------------------------------------------------------------
extern "C" void kernel_launch(void* const* d_in, const int* in_sizes, int n_in,
                              void* d_out, int out_size)
{
    const float* x      = (const float*)d_in[0];   // [4096, 3072]
    const float* W_qkv  = (const float*)d_in[1];   // [3072, 3072]
    const float* W_proj = (const float*)d_in[2];   // [1024, 1024]
    const float* b_proj = (const float*)d_in[3];   // [1024]
    float* out = (float*)d_out;                    // [4096, 1024]

    float* qkv; cudaGetSymbolAddress((void**)&qkv, g_qkv);
    float* att; cudaGetSymbolAddress((void**)&att, g_att);

    cudaFuncSetAttribute(attn_tf32,
                         cudaFuncAttributeMaxDynamicSharedMemorySize, ATTN_SMEM);

    // 1) qkv = x @ W_qkv^T
    {
        dim3 grid(C3 / BN, SEQ / BM);
        gemm_tf32<<<grid, 256>>>(x, W_qkv, nullptr, qkv, SEQ, C3, C3);
    }
    // 2) attention
    {
        dim3 grid(SEQ / AQ, NHEAD);
        attn_tf32<<<grid, 128, ATTN_SMEM>>>(qkv, att);
    }
    // 3) out = att @ W_proj^T + b_proj
    {
        dim3 grid(DIM / BN, SEQ / BM);
        gemm_tf32<<<grid, 256>>>(att, W_proj, b_proj, out, SEQ, DIM, DIM);
    }
}